// round 15
// baseline (speedup 1.0000x reference)
#include <cuda_runtime.h>
#include <cuda_bf16.h>
#include <cstdint>
#include <math.h>

#define Ptot 32768
#define NODES (Ptot*4)
#define Hh 128
#define Ww 128

// ---------------- scratch ----------------
__device__ __nv_bfloat16 g_Xhi[NODES*256], g_Xlo[NODES*256];
__device__ __nv_bfloat16 g_Mhi[Ptot*256],  g_Mlo[Ptot*256];
__device__ __nv_bfloat16 g_H1hi[Ptot*256], g_H1lo[Ptot*256];
__device__ __nv_bfloat16 g_PChi[Ptot*256], g_PClo[Ptot*256];
__device__ __nv_bfloat16 g_Whi[6*65536], g_Wlo[6*65536];    // [mat][n][k]
__device__ __nv_bfloat16 g_CWhi[9*65536], g_CWlo[9*65536];  // [q][co][ci]

// ---------------- PTX helpers ----------------
__device__ __forceinline__ uint32_t cvta_s(const void* p) {
    uint32_t a;
    asm("{ .reg .u64 t; cvta.to.shared.u64 t, %1; cvt.u32.u64 %0, t; }" : "=r"(a) : "l"(p));
    return a;
}
__device__ __forceinline__ void cp16(uint32_t d, const void* s) {
    asm volatile("cp.async.cg.shared.global [%0], [%1], 16;" :: "r"(d), "l"(s));
}
__device__ __forceinline__ void cp16z(uint32_t d, const void* s, int valid) {
    int sz = valid ? 16 : 0;
    asm volatile("cp.async.cg.shared.global [%0], [%1], 16, %2;" :: "r"(d), "l"(s), "r"(sz));
}
#define CP_COMMIT asm volatile("cp.async.commit_group;" ::: "memory")
#define CP_WAIT0  asm volatile("cp.async.wait_group 0;" ::: "memory")
__device__ __forceinline__ void ldsm4(uint32_t* r, uint32_t a) {
    asm volatile("ldmatrix.sync.aligned.m8n8.x4.shared.b16 {%0,%1,%2,%3}, [%4];"
                 : "=r"(r[0]), "=r"(r[1]), "=r"(r[2]), "=r"(r[3]) : "r"(a));
}
__device__ __forceinline__ void mma16816(float* c, const uint32_t* a, const uint32_t* b) {
    asm("mma.sync.aligned.m16n8k16.row.col.f32.bf16.bf16.f32 "
        "{%0,%1,%2,%3},{%4,%5,%6,%7},{%8,%9},{%0,%1,%2,%3};"
        : "+f"(c[0]), "+f"(c[1]), "+f"(c[2]), "+f"(c[3])
        : "r"(a[0]), "r"(a[1]), "r"(a[2]), "r"(a[3]), "r"(b[0]), "r"(b[1]));
}

__device__ __forceinline__ float bfu(uint32_t bits16) {
    return __uint_as_float(bits16 << 16);
}
__device__ __forceinline__ void split2(float a, float b, uint32_t& hi, uint32_t& lo) {
    __nv_bfloat16 ha = __float2bfloat16(a), hb = __float2bfloat16(b);
    __nv_bfloat16 la = __float2bfloat16(a - __bfloat162float(ha));
    __nv_bfloat16 lb = __float2bfloat16(b - __bfloat162float(hb));
    hi = (uint32_t)__bfloat16_as_ushort(ha) | ((uint32_t)__bfloat16_as_ushort(hb) << 16);
    lo = (uint32_t)__bfloat16_as_ushort(la) | ((uint32_t)__bfloat16_as_ushort(lb) << 16);
}

// XOR-swizzled 64B-row layout
#define SWO(r, c) ((uint32_t)((r) * 64 + (((c) ^ ((((r) >> 1) & 3) << 4)))))

// gemm_split smem (64x128 tile): stage = Ahi(4K) Alo(4K) Bhi(8K) Blo(8K) = 24KB; 2 stages
#define GSTG 24576
#define GEMM_SMEM (2*GSTG)
// fused gatv2 smem: stage = Ahi(4K) Alo(4K) Bhi(32K) Blo(32K) = 72KB; 2 stages + satt(1K) + scr(4K)
#define FSTG 73728
#define FSM_SATT 147456
#define FSM_SCR  148480
#define FUSED_SMEM 152576
// conv smem
#define CA 8448
#define BOFF (2*CA)
#define CBUF (BOFF + 6*4096)
#define CONV_SMEM (2*CBUF)

__device__ __forceinline__ const __nv_bfloat16* pick_a(int s) {
    switch (s) {
        case 0: return g_Mhi;  case 1: return g_Mlo;
        case 2: return g_H1hi; case 3: return g_H1lo;
        case 4: return g_Xhi;  default: return g_Xlo;
    }
}
__device__ __forceinline__ __nv_bfloat16* pick_s(int s, int lo) {
    if (s == 1) return lo ? g_H1lo : g_H1hi;
    return lo ? g_Xlo : g_Xhi;
}

// ---------------- prep (single launch) ----------------
struct WPtrs { const float* p[6]; };
__global__ void prep_all(WPtrs wp, const float* __restrict__ cw) {
    int y = blockIdx.y;
    if (y < 6) {
        if (blockIdx.z != 0) return;
        int n = blockIdx.x, k = threadIdx.x;
        float v = wp.p[y][k * 256 + n];
        __nv_bfloat16 h = __float2bfloat16(v);
        g_Whi[(size_t)y * 65536 + n * 256 + k] = h;
        g_Wlo[(size_t)y * 65536 + n * 256 + k] = __float2bfloat16(v - __bfloat162float(h));
    } else {
        int q = y - 6 + blockIdx.z * 3;
        int co = blockIdx.x, ci = threadIdx.x;
        float v = cw[((size_t)co * 256 + ci) * 9 + q];
        __nv_bfloat16 h = __float2bfloat16(v);
        g_CWhi[((size_t)q * 256 + co) * 256 + ci] = h;
        g_CWlo[((size_t)q * 256 + co) * 256 + ci] = __float2bfloat16(v - __bfloat162float(h));
    }
}

// ---------------- NCHW -> node splits + mean splits ----------------
__global__ void build_nodes(const float* __restrict__ m0,
                            const float* __restrict__ m1,
                            const float* __restrict__ m2) {
    __shared__ float s0[32][33], s1[32][33], s2[32][33];
    int ptile = blockIdx.x * 32, c0 = blockIdx.y * 32;
    int tx = threadIdx.x, ty = threadIdx.y;
    int b = ptile >> 14, rem = ptile & 16383;
    int h = rem >> 7, w0 = rem & 127;
#pragma unroll
    for (int i = 0; i < 4; i++) {
        int cl = ty + 8 * i;
        size_t a = (((size_t)(b * 256 + c0 + cl) * Hh + h) * Ww) + w0 + tx;
        s0[cl][tx] = m0[a]; s1[cl][tx] = m1[a]; s2[cl][tx] = m2[a];
    }
    __syncthreads();
#pragma unroll
    for (int i = 0; i < 4; i++) {
        int pl = ty + 8 * i;
        int p = ptile + pl;
        size_t base = (size_t)p * 1024 + c0 + tx;
        float v[3] = { s0[tx][pl], s1[tx][pl], s2[tx][pl] };
#pragma unroll
        for (int j = 0; j < 3; j++) {
            size_t a = base + (j + 1) * 256;
            __nv_bfloat16 h16 = __float2bfloat16(v[j]);
            g_Xhi[a] = h16;
            g_Xlo[a] = __float2bfloat16(v[j] - __bfloat162float(h16));
        }
        float mn = (v[0] + v[1] + v[2]) * (1.0f / 3.0f);
        __nv_bfloat16 mh = __float2bfloat16(mn);
        g_Mhi[(size_t)p * 256 + c0 + tx] = mh;
        g_Mlo[(size_t)p * 256 + c0 + tx] = __float2bfloat16(mn - __bfloat162float(mh));
    }
}

// ---------------- GEMM compute core: per-warp 32x64 fragment (shared by both GEMM kernels) ----------------
__device__ __forceinline__ void frag_compute(uint32_t a0, uint32_t a1, uint32_t b0, uint32_t b1,
                                             int lane, int mwarp, int nwarp, float acc[2][8][4]) {
    int colb = ((lane >> 4) << 4);
#pragma unroll
    for (int ks = 0; ks < 2; ks++) {
        int cb = ks * 32 + colb;
        uint32_t ah[2][4], al[2][4];
#pragma unroll
        for (int mt = 0; mt < 2; mt++) {
            int r = mwarp + mt * 16 + (lane & 15);
            ldsm4(ah[mt], a0 + SWO(r, cb));
            ldsm4(al[mt], a1 + SWO(r, cb));
        }
#pragma unroll
        for (int np = 0; np < 4; np++) {
            int r = nwarp + np * 16 + (lane & 15);
            uint32_t th[4], tl[4];
            ldsm4(th, b0 + SWO(r, cb));
            ldsm4(tl, b1 + SWO(r, cb));
            uint32_t bh0[2] = {th[0], th[2]}, bh1[2] = {th[1], th[3]};
            uint32_t bl0[2] = {tl[0], tl[2]}, bl1[2] = {tl[1], tl[3]};
            mma16816(acc[0][2*np],   ah[0], bh0);
            mma16816(acc[0][2*np+1], ah[0], bh1);
            mma16816(acc[1][2*np],   ah[1], bh0);
            mma16816(acc[1][2*np+1], ah[1], bh1);
            mma16816(acc[0][2*np],   ah[0], bl0);
            mma16816(acc[0][2*np+1], ah[0], bl1);
            mma16816(acc[1][2*np],   ah[1], bl0);
            mma16816(acc[1][2*np+1], ah[1], bl1);
            mma16816(acc[0][2*np],   al[0], bh0);
            mma16816(acc[0][2*np+1], al[0], bh1);
            mma16816(acc[1][2*np],   al[1], bh0);
            mma16816(acc[1][2*np+1], al[1], bh1);
        }
    }
}

// 128 threads: A 2x(64rows x 4), B 2x(128rows x 4)
#define GEMM_LOAD(kc, bf, AHI, ALO, BHI, BLO)                                     \
    do {                                                                          \
        _Pragma("unroll")                                                         \
        for (int i = 0; i < 12; i++) {                                            \
            int idx = i * 128 + tid;                                              \
            int kk = (kc) * 32;                                                   \
            if (idx < 512) {                                                      \
                int arr = idx >> 8, cid = idx & 255, row = cid >> 2;              \
                int off = (cid & 3) * 16;                                         \
                const __nv_bfloat16* src = (arr == 0)                             \
                    ? &AHI[(size_t)(m0 + row) * 256 + kk + (cid & 3) * 8]         \
                    : &ALO[(size_t)(m0 + row) * 256 + kk + (cid & 3) * 8];        \
                cp16(sb + (bf) * GSTG + arr * 4096 + SWO(row, off), src);         \
            } else {                                                              \
                int j = idx - 512;                                                \
                int arr = j >> 9, cid = j & 511, row = cid >> 2;                  \
                int off = (cid & 3) * 16;                                         \
                const __nv_bfloat16* src = (arr == 0)                             \
                    ? &BHI[(size_t)(n0 + row) * 256 + kk + (cid & 3) * 8]         \
                    : &BLO[(size_t)(n0 + row) * 256 + kk + (cid & 3) * 8];        \
                cp16(sb + (bf) * GSTG + 8192 + arr * 8192 + SWO(row, off), src);  \
            }                                                                     \
        }                                                                         \
        CP_COMMIT;                                                                \
    } while (0)

// ---------------- MLP GEMM: split-bf16 out ----------------
__global__ __launch_bounds__(128, 4) void gemm_split(int asel, int widx,
                                                     const float* __restrict__ bias,
                                                     int ssel, int ldc, int dorelu) {
    extern __shared__ char smem[];
    uint32_t sb = cvta_s(smem);
    int tid = threadIdx.x, lane = tid & 31, wid = tid >> 5;
    int m0 = blockIdx.x * 64, n0 = blockIdx.y * 128;
    int mwarp = (wid & 1) * 32, nwarp = (wid >> 1) * 64;
    const __nv_bfloat16* Ahi = pick_a(asel);
    const __nv_bfloat16* Alo = pick_a(asel + 1);
    const __nv_bfloat16* Bhi = g_Whi + (size_t)widx * 65536;
    const __nv_bfloat16* Blo = g_Wlo + (size_t)widx * 65536;

    float acc[2][8][4] = {};

    GEMM_LOAD(0, 0, Ahi, Alo, Bhi, Blo);
    for (int kc = 0; kc < 8; kc++) {
        CP_WAIT0;
        __syncthreads();
        if (kc < 7) GEMM_LOAD(kc + 1, (kc + 1) & 1, Ahi, Alo, Bhi, Blo);
        uint32_t a0 = sb + (kc & 1) * GSTG;
        frag_compute(a0, a0 + 4096, a0 + 8192, a0 + 16384, lane, mwarp, nwarp, acc);
    }

    __nv_bfloat16* Shi = pick_s(ssel, 0);
    __nv_bfloat16* Slo = pick_s(ssel, 1);
#pragma unroll
    for (int mt = 0; mt < 2; mt++)
#pragma unroll
        for (int nt = 0; nt < 8; nt++) {
            int m = m0 + mwarp + mt * 16 + (lane >> 2);
            int n = n0 + nwarp + nt * 8 + 2 * (lane & 3);
            float bv0 = bias[n], bv1 = bias[n + 1];
            float d0 = acc[mt][nt][0] + bv0, d1 = acc[mt][nt][1] + bv1;
            float d2 = acc[mt][nt][2] + bv0, d3 = acc[mt][nt][3] + bv1;
            if (dorelu) {
                d0 = fmaxf(d0, 0.f); d1 = fmaxf(d1, 0.f);
                d2 = fmaxf(d2, 0.f); d3 = fmaxf(d3, 0.f);
            }
            size_t r0 = (size_t)m * ldc + n, r1 = (size_t)(m + 8) * ldc + n;
            uint32_t h01, l01, h23, l23;
            split2(d0, d1, h01, l01);
            split2(d2, d3, h23, l23);
            *(uint32_t*)&Shi[r0] = h01; *(uint32_t*)&Slo[r0] = l01;
            *(uint32_t*)&Shi[r1] = h23; *(uint32_t*)&Slo[r1] = l23;
        }
}

// ---------------- FUSED GATv2 layer: [XL|XR] GEMM + attention + softmax + residual + LN ----------------
// 512 threads, tile 64 rows (16 pixels) x 512 cols. 16 warps: mwarp=(wid&1)*32, nwarp=(wid>>1)*64.
__global__ __launch_bounds__(512, 1) void gatv2_fused(
        int wbase, const float* __restrict__ bl, const float* __restrict__ br,
        const float* __restrict__ att, const float* __restrict__ gbias,
        const float* __restrict__ lng, const float* __restrict__ lnb, int writePC) {
    extern __shared__ char smem[];
    uint32_t sb = cvta_s(smem);
    int tid = threadIdx.x, lane = tid & 31, wid = tid >> 5;
    int m0 = blockIdx.x * 64;
    int mwarp = (wid & 1) * 32, nwarp = (wid >> 1) * 64;
    const __nv_bfloat16* BhiL = g_Whi + (size_t)wbase * 65536;
    const __nv_bfloat16* BloL = g_Wlo + (size_t)wbase * 65536;
    const __nv_bfloat16* BhiR = g_Whi + (size_t)(wbase + 1) * 65536;
    const __nv_bfloat16* BloR = g_Wlo + (size_t)(wbase + 1) * 65536;
    float* satt = (float*)(smem + FSM_SATT);
    float* sscr = (float*)(smem + FSM_SCR);
    if (tid < 64) *(float4*)&satt[tid * 4] = *(const float4*)&att[tid * 4];

    float acc[2][8][4] = {};

    auto load = [&](int kc, int bf) {
        int kk = kc * 32;
        uint32_t stg = sb + bf * FSTG;
#pragma unroll
        for (int i = 0; i < 9; i++) {
            int idx = i * 512 + tid;
            if (idx < 512) {
                int arr = idx >> 8, cid = idx & 255, row = cid >> 2;
                int off = (cid & 3) * 16;
                const __nv_bfloat16* src = (arr == 0)
                    ? &g_Xhi[(size_t)(m0 + row) * 256 + kk + (cid & 3) * 8]
                    : &g_Xlo[(size_t)(m0 + row) * 256 + kk + (cid & 3) * 8];
                cp16(stg + arr * 4096 + SWO(row, off), src);
            } else {
                int j = idx - 512;
                int arr = j >> 11, cid = j & 2047, row = cid >> 2;
                int off = (cid & 3) * 16;
                const __nv_bfloat16* basep = (arr == 0)
                    ? (row < 256 ? BhiL + (size_t)row * 256 : BhiR + (size_t)(row - 256) * 256)
                    : (row < 256 ? BloL + (size_t)row * 256 : BloR + (size_t)(row - 256) * 256);
                cp16(stg + 8192 + arr * 32768 + SWO(row, off), basep + kk + (cid & 3) * 8);
            }
        }
        CP_COMMIT;
    };

    load(0, 0);
    for (int kc = 0; kc < 8; kc++) {
        CP_WAIT0;
        __syncthreads();
        if (kc < 7) load(kc + 1, (kc + 1) & 1);
        uint32_t a0 = sb + (kc & 1) * FSTG;
        frag_compute(a0, a0 + 4096, a0 + 8192, a0 + 8192 + 32768, lane, mwarp, nwarp, acc);
    }
    __syncthreads();

    // store accs (+linear bias) to smem fp32: sxl = [64][256] at 0, sxr at 64KB
    float* sx = (float*)smem;
#pragma unroll
    for (int mt = 0; mt < 2; mt++)
#pragma unroll
        for (int nt = 0; nt < 8; nt++) {
            int m = mwarp + mt * 16 + (lane >> 2);
            int n = nwarp + nt * 8 + 2 * (lane & 3);
            const float* bb = (n < 256) ? (bl + n) : (br + n - 256);
            float bv0 = bb[0], bv1 = bb[1];
            int base = (n >> 8) * 16384 + (n & 255);
            sx[base + m * 256]           = acc[mt][nt][0] + bv0;
            sx[base + m * 256 + 1]       = acc[mt][nt][1] + bv1;
            sx[base + (m + 8) * 256]     = acc[mt][nt][2] + bv0;
            sx[base + (m + 8) * 256 + 1] = acc[mt][nt][3] + bv1;
        }
    __syncthreads();

    // attention: one warp per pixel (16 pixels)
    float* sxl = (float*)smem;
    float* sxr = sxl + 16384;
    int w = wid;
    float* scr = sscr + w * 64;
    // scores: t = i*16 + j*4 + h
    for (int t = 0; t < 64; t++) {
        int i = t >> 4, j = (t >> 2) & 3, h = t & 3;
        int c = h * 64 + 2 * lane;
        int ri = 4 * w + i, rj = 4 * w + j;
        float v0 = sxr[ri * 256 + c]     + sxl[rj * 256 + c];
        float v1 = sxr[ri * 256 + c + 1] + sxl[rj * 256 + c + 1];
        v0 = v0 > 0.f ? v0 : 0.2f * v0;
        v1 = v1 > 0.f ? v1 : 0.2f * v1;
        float partial = satt[c] * v0 + satt[c + 1] * v1;
#pragma unroll
        for (int off = 16; off; off >>= 1)
            partial += __shfl_xor_sync(0xffffffffu, partial, off);
        if (lane == 0) scr[t] = partial;
    }
    __syncwarp();
    if (lane < 16) {
        int i = lane >> 2, h = lane & 3;
        float s0 = scr[i * 16 + 0 + h], s1 = scr[i * 16 + 4 + h];
        float s2 = scr[i * 16 + 8 + h], s3 = scr[i * 16 + 12 + h];
        float mx = fmaxf(fmaxf(s0, s1), fmaxf(s2, s3));
        float e0 = expf(s0 - mx), e1 = expf(s1 - mx), e2 = expf(s2 - mx), e3 = expf(s3 - mx);
        float inv = 1.f / (e0 + e1 + e2 + e3);
        scr[i * 16 + 0 + h] = e0 * inv;  scr[i * 16 + 4 + h] = e1 * inv;
        scr[i * 16 + 8 + h] = e2 * inv;  scr[i * 16 + 12 + h] = e3 * inv;
    }
    __syncwarp();

    int p = blockIdx.x * 16 + w;
#pragma unroll
    for (int i = 0; i < 4; i++) {
        float stv[8];
        float sum = 0.f, sq = 0.f;
#pragma unroll
        for (int u = 0; u < 4; u++) {
            int c = 2 * lane + 64 * u;           // h = u (2*lane < 64)
            float a0 = scr[i * 16 + 0 + u], a1 = scr[i * 16 + 4 + u];
            float a2 = scr[i * 16 + 8 + u], a3 = scr[i * 16 + 12 + u];
            float2 x0 = *(float2*)&sxl[(4 * w + 0) * 256 + c];
            float2 x1 = *(float2*)&sxl[(4 * w + 1) * 256 + c];
            float2 x2 = *(float2*)&sxl[(4 * w + 2) * 256 + c];
            float2 x3 = *(float2*)&sxl[(4 * w + 3) * 256 + c];
            float o0 = a0 * x0.x + a1 * x1.x + a2 * x2.x + a3 * x3.x;
            float o1 = a0 * x0.y + a1 * x1.y + a2 * x2.y + a3 * x3.y;
            size_t ga = (size_t)(m0 + 4 * w + i) * 256 + c;
            uint32_t rh = *(const uint32_t*)&g_Xhi[ga];
            uint32_t rl = *(const uint32_t*)&g_Xlo[ga];
            float st0 = o0 + gbias[c]     + bfu(rh & 0xffff) + bfu(rl & 0xffff);
            float st1 = o1 + gbias[c + 1] + bfu(rh >> 16)    + bfu(rl >> 16);
            stv[2 * u] = st0; stv[2 * u + 1] = st1;
            sum += st0 + st1; sq += st0 * st0 + st1 * st1;
        }
#pragma unroll
        for (int off = 16; off; off >>= 1) {
            sum += __shfl_xor_sync(0xffffffffu, sum, off);
            sq  += __shfl_xor_sync(0xffffffffu, sq, off);
        }
        float mu = sum * (1.f / 256.f);
        float var = sq * (1.f / 256.f) - mu * mu;
        float rstd = rsqrtf(var + 1e-5f);
#pragma unroll
        for (int u = 0; u < 4; u++) {
            int c = 2 * lane + 64 * u;
            float y0 = (stv[2 * u]     - mu) * rstd * lng[c]     + lnb[c];
            float y1 = (stv[2 * u + 1] - mu) * rstd * lng[c + 1] + lnb[c + 1];
            uint32_t h, l;
            split2(y0, y1, h, l);
            size_t ga = (size_t)(m0 + 4 * w + i) * 256 + c;
            *(uint32_t*)&g_Xhi[ga] = h;
            *(uint32_t*)&g_Xlo[ga] = l;
            if (writePC && i == 0) {
                *(uint32_t*)&g_PChi[(size_t)p * 256 + c] = h;
                *(uint32_t*)&g_PClo[(size_t)p * 256 + c] = l;
            }
        }
    }
}

// ---------------- conv3x3+BN+ReLU+residual: halo A-tile shared across 3 dw shifts ----------------
__global__ __launch_bounds__(256, 2) void conv_mma(const float* __restrict__ bg,
                                                   const float* __restrict__ bb,
                                                   const float* __restrict__ bm,
                                                   const float* __restrict__ bv,
                                                   float* __restrict__ out) {
    extern __shared__ char smem[];
    uint32_t sb = cvta_s(smem);
    int tid = threadIdx.x, lane = tid & 31, wid = tid >> 5;
    int tile = blockIdx.x;
    int n0 = blockIdx.y * 64;
    int p0 = tile * 128;
    int b = tile >> 7, h = tile & 127;
    int mwarp = (wid & 3) * 32, nwarp = (wid >> 2) * 32;

    int dhs[3], nv = 0;
    for (int dh = -1; dh <= 1; dh++)
        if ((unsigned)(h + dh) < 128u) dhs[nv++] = dh;
    int S = nv * 8;

    float acc[2][4][4] = {};

    auto load_phase = [&](int s, int bf) {
        int dh = dhs[s >> 3], kc = s & 7;
        uint32_t stg = sb + bf * CBUF;
        int kk0 = kc * 32;
#pragma unroll
        for (int i = 0; i < 5; i++) {
            int idx = i * 256 + tid;
            if (idx < 1040) {
                int arr = idx >= 520;
                int cid = arr ? idx - 520 : idx;
                int row = cid >> 2, off = (cid & 3) * 16;
                int wpix = row - 1;
                int valid = (unsigned)wpix < 128u;
                int gp = p0 + dh * 128 + (valid ? wpix : 0);
                const __nv_bfloat16* src = (arr == 0)
                    ? &g_PChi[(size_t)gp * 256 + kk0 + (cid & 3) * 8]
                    : &g_PClo[(size_t)gp * 256 + kk0 + (cid & 3) * 8];
                cp16z(stg + arr * CA + SWO(row, off), src, valid);
            }
        }
        int qbase = (dh + 1) * 3;
#pragma unroll
        for (int i = 0; i < 6; i++) {
            int idx = i * 256 + tid;
            int qq = idx >> 9, r2 = idx & 511;
            int isLo = r2 >> 8, cid = r2 & 255;
            int row = cid >> 2, off = (cid & 3) * 16;
            const __nv_bfloat16* basep = isLo ? g_CWlo : g_CWhi;
            cp16(stg + BOFF + qq * 8192 + isLo * 4096 + SWO(row, off),
                 &basep[(size_t)(qbase + qq) * 65536 + (size_t)(n0 + row) * 256 + kk0 + (cid & 3) * 8]);
        }
        CP_COMMIT;
    };

    auto compute = [&](int bf) {
        uint32_t stg = sb + bf * CBUF;
        int colb = ((lane >> 4) << 4);
#pragma unroll
        for (int dwq = 0; dwq < 3; dwq++) {
            uint32_t b0 = stg + BOFF + dwq * 8192;
            uint32_t b1 = b0 + 4096;
#pragma unroll
            for (int ks = 0; ks < 2; ks++) {
                int cb = ks * 32 + colb;
                uint32_t ah[2][4], al[2][4];
#pragma unroll
                for (int mt = 0; mt < 2; mt++) {
                    int r = mwarp + mt * 16 + (lane & 15) + dwq;
                    ldsm4(ah[mt], stg + SWO(r, cb));
                    ldsm4(al[mt], stg + CA + SWO(r, cb));
                }
#pragma unroll
                for (int np = 0; np < 2; np++) {
                    int r = nwarp + np * 16 + (lane & 15);
                    uint32_t th[4], tl[4];
                    ldsm4(th, b0 + SWO(r, cb));
                    ldsm4(tl, b1 + SWO(r, cb));
                    uint32_t bh0[2] = {th[0], th[2]}, bh1[2] = {th[1], th[3]};
                    uint32_t bl0[2] = {tl[0], tl[2]}, bl1[2] = {tl[1], tl[3]};
                    mma16816(acc[0][2*np],   ah[0], bh0);
                    mma16816(acc[0][2*np+1], ah[0], bh1);
                    mma16816(acc[1][2*np],   ah[1], bh0);
                    mma16816(acc[1][2*np+1], ah[1], bh1);
                    mma16816(acc[0][2*np],   ah[0], bl0);
                    mma16816(acc[0][2*np+1], ah[0], bl1);
                    mma16816(acc[1][2*np],   ah[1], bl0);
                    mma16816(acc[1][2*np+1], ah[1], bl1);
                    mma16816(acc[0][2*np],   al[0], bh0);
                    mma16816(acc[0][2*np+1], al[0], bh1);
                    mma16816(acc[1][2*np],   al[1], bh0);
                    mma16816(acc[1][2*np+1], al[1], bh1);
                }
            }
        }
    };

    load_phase(0, 0);
    for (int s = 0; s < S; s++) {
        CP_WAIT0;
        __syncthreads();
        if (s + 1 < S) load_phase(s + 1, (s + 1) & 1);
        compute(s & 1);
    }

#pragma unroll
    for (int mt = 0; mt < 2; mt++)
#pragma unroll
        for (int nt = 0; nt < 4; nt++) {
            int w = mwarp + mt * 16 + (lane >> 2);
            int co = n0 + nwarp + nt * 8 + 2 * (lane & 3);
            float sc0 = bg[co] * rsqrtf(bv[co] + 1e-5f);
            float sh0 = bb[co] - bm[co] * sc0;
            float sc1 = bg[co+1] * rsqrtf(bv[co+1] + 1e-5f);
            float sh1 = bb[co+1] - bm[co+1] * sc1;
            float d[4] = {
                fmaf(acc[mt][nt][0], sc0, sh0), fmaf(acc[mt][nt][1], sc1, sh1),
                fmaf(acc[mt][nt][2], sc0, sh0), fmaf(acc[mt][nt][3], sc1, sh1) };
#pragma unroll
            for (int e = 0; e < 4; e++) d[e] = fmaxf(d[e], 0.f);
            int w2 = w + 8;
            uint32_t rh0 = *(const uint32_t*)&g_PChi[(size_t)(p0 + w) * 256 + co];
            uint32_t rl0 = *(const uint32_t*)&g_PClo[(size_t)(p0 + w) * 256 + co];
            uint32_t rh1 = *(const uint32_t*)&g_PChi[(size_t)(p0 + w2) * 256 + co];
            uint32_t rl1 = *(const uint32_t*)&g_PClo[(size_t)(p0 + w2) * 256 + co];
            d[0] += bfu(rh0 & 0xffff) + bfu(rl0 & 0xffff);
            d[1] += bfu(rh0 >> 16)    + bfu(rl0 >> 16);
            d[2] += bfu(rh1 & 0xffff) + bfu(rl1 & 0xffff);
            d[3] += bfu(rh1 >> 16)    + bfu(rl1 >> 16);
            out[(((size_t)(b * 256 + co)) * Hh + h) * Ww + w]       = d[0];
            out[(((size_t)(b * 256 + co + 1)) * Hh + h) * Ww + w]   = d[1];
            out[(((size_t)(b * 256 + co)) * Hh + h) * Ww + w2]      = d[2];
            out[(((size_t)(b * 256 + co + 1)) * Hh + h) * Ww + w2]  = d[3];
        }
}

// ---------------- launch ----------------
extern "C" void kernel_launch(void* const* d_in, const int* in_sizes, int n_in,
                              void* d_out, int out_size) {
    const float* m0 = (const float*)d_in[0];
    const float* m1 = (const float*)d_in[1];
    const float* m2 = (const float*)d_in[2];
    const float* fn_w1 = (const float*)d_in[3];
    const float* fn_b1 = (const float*)d_in[4];
    const float* fn_w2 = (const float*)d_in[5];
    const float* fn_b2 = (const float*)d_in[6];
    const float* l_wl[2]  = {(const float*)d_in[7],  (const float*)d_in[15]};
    const float* l_bl[2]  = {(const float*)d_in[8],  (const float*)d_in[16]};
    const float* l_wr[2]  = {(const float*)d_in[9],  (const float*)d_in[17]};
    const float* l_br[2]  = {(const float*)d_in[10], (const float*)d_in[18]};
    const float* l_att[2] = {(const float*)d_in[11], (const float*)d_in[19]};
    const float* l_bi[2]  = {(const float*)d_in[12], (const float*)d_in[20]};
    const float* ln_g[2]  = {(const float*)d_in[13], (const float*)d_in[21]};
    const float* ln_b[2]  = {(const float*)d_in[14], (const float*)d_in[22]};
    const float* conv_w = (const float*)d_in[23];
    const float* bn_g = (const float*)d_in[24];
    const float* bn_b = (const float*)d_in[25];
    const float* bn_m = (const float*)d_in[26];
    const float* bn_v = (const float*)d_in[27];
    float* out = (float*)d_out;

    static int inited = 0;
    if (!inited) {
        cudaFuncSetAttribute(gemm_split,  cudaFuncAttributeMaxDynamicSharedMemorySize, GEMM_SMEM);
        cudaFuncSetAttribute(gatv2_fused, cudaFuncAttributeMaxDynamicSharedMemorySize, FUSED_SMEM);
        cudaFuncSetAttribute(conv_mma,    cudaFuncAttributeMaxDynamicSharedMemorySize, CONV_SMEM);
        inited = 1;
    }

    WPtrs wp;
    wp.p[0] = fn_w1; wp.p[1] = fn_w2;
    wp.p[2] = l_wl[0]; wp.p[3] = l_wr[0];
    wp.p[4] = l_wl[1]; wp.p[5] = l_wr[1];
    prep_all<<<dim3(256, 9, 3), 256>>>(wp, conv_w);

    build_nodes<<<dim3(Ptot / 32, 256 / 32), dim3(32, 8)>>>(m0, m1, m2);

    // fusion MLP: H1 = relu(mean@W1+b1); X node0 = H1@W2+b2
    gemm_split<<<dim3(Ptot / 64, 2), 128, GEMM_SMEM>>>(0, 0, fn_b1, 1, 256, 1);
    gemm_split<<<dim3(Ptot / 64, 2), 128, GEMM_SMEM>>>(2, 1, fn_b2, 2, 1024, 0);

    for (int l = 0; l < 2; l++) {
        gatv2_fused<<<NODES / 64, 512, FUSED_SMEM>>>(
            2 + 2 * l, l_bl[l], l_br[l], l_att[l], l_bi[l], ln_g[l], ln_b[l], l == 1);
    }

    conv_mma<<<dim3(256, 4), 256, CONV_SMEM>>>(bn_g, bn_b, bn_m, bn_v, out);
}

// round 16
// speedup vs baseline: 1.0819x; 1.0819x over previous
#include <cuda_runtime.h>
#include <cuda_bf16.h>
#include <cstdint>
#include <math.h>

#define Ptot 32768
#define NODES (Ptot*4)
#define Hh 128
#define Ww 128

// ---------------- scratch ----------------
__device__ float g_XL[NODES*256];
__device__ float g_XR[NODES*256];
__device__ __nv_bfloat16 g_Xhi[NODES*256], g_Xlo[NODES*256];
__device__ __nv_bfloat16 g_Mhi[Ptot*256],  g_Mlo[Ptot*256];
__device__ __nv_bfloat16 g_H1hi[Ptot*256], g_H1lo[Ptot*256];
__device__ __nv_bfloat16 g_PChi[Ptot*256], g_PClo[Ptot*256];
__device__ __nv_bfloat16 g_Whi[6*65536], g_Wlo[6*65536];    // [mat][n][k]
__device__ __nv_bfloat16 g_CWhi[9*65536], g_CWlo[9*65536];  // [q][co][ci]

// ---------------- PTX helpers ----------------
__device__ __forceinline__ uint32_t cvta_s(const void* p) {
    uint32_t a;
    asm("{ .reg .u64 t; cvta.to.shared.u64 t, %1; cvt.u32.u64 %0, t; }" : "=r"(a) : "l"(p));
    return a;
}
__device__ __forceinline__ void cp16(uint32_t d, const void* s) {
    asm volatile("cp.async.cg.shared.global [%0], [%1], 16;" :: "r"(d), "l"(s));
}
__device__ __forceinline__ void cp16z(uint32_t d, const void* s, int valid) {
    int sz = valid ? 16 : 0;
    asm volatile("cp.async.cg.shared.global [%0], [%1], 16, %2;" :: "r"(d), "l"(s), "r"(sz));
}
#define CP_COMMIT asm volatile("cp.async.commit_group;" ::: "memory")
#define CP_WAIT0  asm volatile("cp.async.wait_group 0;" ::: "memory")
__device__ __forceinline__ void ldsm4(uint32_t* r, uint32_t a) {
    asm volatile("ldmatrix.sync.aligned.m8n8.x4.shared.b16 {%0,%1,%2,%3}, [%4];"
                 : "=r"(r[0]), "=r"(r[1]), "=r"(r[2]), "=r"(r[3]) : "r"(a));
}
__device__ __forceinline__ void mma16816(float* c, const uint32_t* a, const uint32_t* b) {
    asm("mma.sync.aligned.m16n8k16.row.col.f32.bf16.bf16.f32 "
        "{%0,%1,%2,%3},{%4,%5,%6,%7},{%8,%9},{%0,%1,%2,%3};"
        : "+f"(c[0]), "+f"(c[1]), "+f"(c[2]), "+f"(c[3])
        : "r"(a[0]), "r"(a[1]), "r"(a[2]), "r"(a[3]), "r"(b[0]), "r"(b[1]));
}

__device__ __forceinline__ float bfu(uint32_t bits16) {
    return __uint_as_float(bits16 << 16);
}
__device__ __forceinline__ void split2(float a, float b, uint32_t& hi, uint32_t& lo) {
    __nv_bfloat16 ha = __float2bfloat16(a), hb = __float2bfloat16(b);
    __nv_bfloat16 la = __float2bfloat16(a - __bfloat162float(ha));
    __nv_bfloat16 lb = __float2bfloat16(b - __bfloat162float(hb));
    hi = (uint32_t)__bfloat16_as_ushort(ha) | ((uint32_t)__bfloat16_as_ushort(hb) << 16);
    lo = (uint32_t)__bfloat16_as_ushort(la) | ((uint32_t)__bfloat16_as_ushort(lb) << 16);
}

// XOR-swizzled 64B-row layout (conflict-free for ldmatrix + cp.async 16B chunks)
#define SWO(r, c) ((uint32_t)((r) * 64 + (((c) ^ ((((r) >> 1) & 3) << 4)))))

// gemm smem (64x128 tile): stage = Ahi(4K) Alo(4K) Bhi(8K) Blo(8K) = 24KB; 2 stages
#define GSTG 24576
#define GEMM_SMEM (2*GSTG)
// conv smem: 2 stages x (A halo: 2x132x64B, B: 3q x 2 x 64x64B)
#define CA 8448
#define BOFF (2*CA)
#define CBUF (BOFF + 6*4096)
#define CONV_SMEM (2*CBUF)

__device__ __forceinline__ const __nv_bfloat16* pick_a(int s) {
    switch (s) {
        case 0: return g_Mhi;  case 1: return g_Mlo;
        case 2: return g_H1hi; case 3: return g_H1lo;
        case 4: return g_Xhi;  default: return g_Xlo;
    }
}
__device__ __forceinline__ __nv_bfloat16* pick_s(int s, int lo) {
    if (s == 1) return lo ? g_H1lo : g_H1hi;
    return lo ? g_Xlo : g_Xhi;
}

// ---------------- prep (single launch) ----------------
struct WPtrs { const float* p[6]; };
__global__ void prep_all(WPtrs wp, const float* __restrict__ cw) {
    int y = blockIdx.y;
    if (y < 6) {
        if (blockIdx.z != 0) return;
        int n = blockIdx.x, k = threadIdx.x;
        float v = wp.p[y][k * 256 + n];
        __nv_bfloat16 h = __float2bfloat16(v);
        g_Whi[(size_t)y * 65536 + n * 256 + k] = h;
        g_Wlo[(size_t)y * 65536 + n * 256 + k] = __float2bfloat16(v - __bfloat162float(h));
    } else {
        int q = y - 6 + blockIdx.z * 3;
        int co = blockIdx.x, ci = threadIdx.x;
        float v = cw[((size_t)co * 256 + ci) * 9 + q];
        __nv_bfloat16 h = __float2bfloat16(v);
        g_CWhi[((size_t)q * 256 + co) * 256 + ci] = h;
        g_CWlo[((size_t)q * 256 + co) * 256 + ci] = __float2bfloat16(v - __bfloat162float(h));
    }
}

// ---------------- NCHW -> node splits + mean splits ----------------
__global__ void build_nodes(const float* __restrict__ m0,
                            const float* __restrict__ m1,
                            const float* __restrict__ m2) {
    __shared__ float s0[32][33], s1[32][33], s2[32][33];
    int ptile = blockIdx.x * 32, c0 = blockIdx.y * 32;
    int tx = threadIdx.x, ty = threadIdx.y;
    int b = ptile >> 14, rem = ptile & 16383;
    int h = rem >> 7, w0 = rem & 127;
#pragma unroll
    for (int i = 0; i < 4; i++) {
        int cl = ty + 8 * i;
        size_t a = (((size_t)(b * 256 + c0 + cl) * Hh + h) * Ww) + w0 + tx;
        s0[cl][tx] = m0[a]; s1[cl][tx] = m1[a]; s2[cl][tx] = m2[a];
    }
    __syncthreads();
#pragma unroll
    for (int i = 0; i < 4; i++) {
        int pl = ty + 8 * i;
        int p = ptile + pl;
        size_t base = (size_t)p * 1024 + c0 + tx;
        float v[3] = { s0[tx][pl], s1[tx][pl], s2[tx][pl] };
#pragma unroll
        for (int j = 0; j < 3; j++) {
            size_t a = base + (j + 1) * 256;
            __nv_bfloat16 h16 = __float2bfloat16(v[j]);
            g_Xhi[a] = h16;
            g_Xlo[a] = __float2bfloat16(v[j] - __bfloat162float(h16));
        }
        float mn = (v[0] + v[1] + v[2]) * (1.0f / 3.0f);
        __nv_bfloat16 mh = __float2bfloat16(mn);
        g_Mhi[(size_t)p * 256 + c0 + tx] = mh;
        g_Mlo[(size_t)p * 256 + c0 + tx] = __float2bfloat16(mn - __bfloat162float(mh));
    }
}

// ---------------- GEMM compute core (64x128 tile, 4 warps) ----------------
__device__ __forceinline__ void gemm_compute(uint32_t sb, int bf, int lane,
                                             int mwarp, int nwarp, float acc[2][8][4]) {
    uint32_t a0 = sb + bf * GSTG;
    uint32_t a1 = a0 + 4096;
    uint32_t b0 = a0 + 8192;
    uint32_t b1 = a0 + 16384;
    int colb = ((lane >> 4) << 4);  // 0 or 16 bytes
#pragma unroll
    for (int ks = 0; ks < 2; ks++) {
        int cb = ks * 32 + colb;
        uint32_t ah[2][4], al[2][4];
#pragma unroll
        for (int mt = 0; mt < 2; mt++) {
            int r = mwarp + mt * 16 + (lane & 15);
            ldsm4(ah[mt], a0 + SWO(r, cb));
            ldsm4(al[mt], a1 + SWO(r, cb));
        }
#pragma unroll
        for (int np = 0; np < 4; np++) {
            int r = nwarp + np * 16 + (lane & 15);
            uint32_t th[4], tl[4];
            ldsm4(th, b0 + SWO(r, cb));
            ldsm4(tl, b1 + SWO(r, cb));
            uint32_t bh0[2] = {th[0], th[2]}, bh1[2] = {th[1], th[3]};
            uint32_t bl0[2] = {tl[0], tl[2]}, bl1[2] = {tl[1], tl[3]};
            mma16816(acc[0][2*np],   ah[0], bh0);
            mma16816(acc[0][2*np+1], ah[0], bh1);
            mma16816(acc[1][2*np],   ah[1], bh0);
            mma16816(acc[1][2*np+1], ah[1], bh1);
            mma16816(acc[0][2*np],   ah[0], bl0);
            mma16816(acc[0][2*np+1], ah[0], bl1);
            mma16816(acc[1][2*np],   ah[1], bl0);
            mma16816(acc[1][2*np+1], ah[1], bl1);
            mma16816(acc[0][2*np],   al[0], bh0);
            mma16816(acc[0][2*np+1], al[0], bh1);
            mma16816(acc[1][2*np],   al[1], bh0);
            mma16816(acc[1][2*np+1], al[1], bh1);
        }
    }
}

// 128 threads, 1536 cp16 chunks: A 2x(64rows x 4), B 2x(128rows x 4)
#define GEMM_LOAD(kc, bf, AHI, ALO, BHI, BLO)                                     \
    do {                                                                          \
        _Pragma("unroll")                                                         \
        for (int i = 0; i < 12; i++) {                                            \
            int idx = i * 128 + tid;                                              \
            int kk = (kc) * 32;                                                   \
            if (idx < 512) {                                                      \
                int arr = idx >> 8, cid = idx & 255, row = cid >> 2;              \
                int off = (cid & 3) * 16;                                         \
                const __nv_bfloat16* src = (arr == 0)                             \
                    ? &AHI[(size_t)(m0 + row) * 256 + kk + (cid & 3) * 8]         \
                    : &ALO[(size_t)(m0 + row) * 256 + kk + (cid & 3) * 8];        \
                cp16(sb + (bf) * GSTG + arr * 4096 + SWO(row, off), src);         \
            } else {                                                              \
                int j = idx - 512;                                                \
                int arr = j >> 9, cid = j & 511, row = cid >> 2;                  \
                int off = (cid & 3) * 16;                                         \
                const __nv_bfloat16* src = (arr == 0)                             \
                    ? &BHI[(size_t)(n0 + row) * 256 + kk + (cid & 3) * 8]         \
                    : &BLO[(size_t)(n0 + row) * 256 + kk + (cid & 3) * 8];        \
                cp16(sb + (bf) * GSTG + 8192 + arr * 8192 + SWO(row, off), src);  \
            }                                                                     \
        }                                                                         \
        CP_COMMIT;                                                                \
    } while (0)

// ---------------- merged GATv2 linear: [XL|XR] = X @ [Wl|Wr], fp32 out ----------------
__global__ __launch_bounds__(128, 4) void gemm_cat(int wbase,
                                                   const float* __restrict__ bl,
                                                   const float* __restrict__ br) {
    extern __shared__ char smem[];
    uint32_t sb = cvta_s(smem);
    int tid = threadIdx.x, lane = tid & 31, wid = tid >> 5;
    int ny = blockIdx.y;
    int m0 = blockIdx.x * 64, n0 = (ny & 1) * 128;
    int widx = wbase + (ny >> 1);
    const float* bias = (ny < 2) ? bl : br;
    float* Cf = (ny < 2) ? g_XL : g_XR;
    int mwarp = (wid & 1) * 32, nwarp = (wid >> 1) * 64;
    const __nv_bfloat16* Bhi = g_Whi + (size_t)widx * 65536;
    const __nv_bfloat16* Blo = g_Wlo + (size_t)widx * 65536;

    float acc[2][8][4] = {};

    GEMM_LOAD(0, 0, g_Xhi, g_Xlo, Bhi, Blo);
    for (int kc = 0; kc < 8; kc++) {
        CP_WAIT0;
        __syncthreads();
        if (kc < 7) GEMM_LOAD(kc + 1, (kc + 1) & 1, g_Xhi, g_Xlo, Bhi, Blo);
        gemm_compute(sb, kc & 1, lane, mwarp, nwarp, acc);
    }

#pragma unroll
    for (int mt = 0; mt < 2; mt++)
#pragma unroll
        for (int nt = 0; nt < 8; nt++) {
            int m = m0 + mwarp + mt * 16 + (lane >> 2);
            int n = n0 + nwarp + nt * 8 + 2 * (lane & 3);
            float bv0 = bias[n], bv1 = bias[n + 1];
            *(float2*)&Cf[(size_t)m * 256 + n] =
                make_float2(acc[mt][nt][0] + bv0, acc[mt][nt][1] + bv1);
            *(float2*)&Cf[(size_t)(m + 8) * 256 + n] =
                make_float2(acc[mt][nt][2] + bv0, acc[mt][nt][3] + bv1);
        }
}

// ---------------- MLP GEMM: split-bf16 out ----------------
__global__ __launch_bounds__(128, 4) void gemm_split(int asel, int widx,
                                                     const float* __restrict__ bias,
                                                     int ssel, int ldc, int dorelu) {
    extern __shared__ char smem[];
    uint32_t sb = cvta_s(smem);
    int tid = threadIdx.x, lane = tid & 31, wid = tid >> 5;
    int m0 = blockIdx.x * 64, n0 = blockIdx.y * 128;
    int mwarp = (wid & 1) * 32, nwarp = (wid >> 1) * 64;
    const __nv_bfloat16* Ahi = pick_a(asel);
    const __nv_bfloat16* Alo = pick_a(asel + 1);
    const __nv_bfloat16* Bhi = g_Whi + (size_t)widx * 65536;
    const __nv_bfloat16* Blo = g_Wlo + (size_t)widx * 65536;

    float acc[2][8][4] = {};

    GEMM_LOAD(0, 0, Ahi, Alo, Bhi, Blo);
    for (int kc = 0; kc < 8; kc++) {
        CP_WAIT0;
        __syncthreads();
        if (kc < 7) GEMM_LOAD(kc + 1, (kc + 1) & 1, Ahi, Alo, Bhi, Blo);
        gemm_compute(sb, kc & 1, lane, mwarp, nwarp, acc);
    }

    __nv_bfloat16* Shi = pick_s(ssel, 0);
    __nv_bfloat16* Slo = pick_s(ssel, 1);
#pragma unroll
    for (int mt = 0; mt < 2; mt++)
#pragma unroll
        for (int nt = 0; nt < 8; nt++) {
            int m = m0 + mwarp + mt * 16 + (lane >> 2);
            int n = n0 + nwarp + nt * 8 + 2 * (lane & 3);
            float bv0 = bias[n], bv1 = bias[n + 1];
            float d0 = acc[mt][nt][0] + bv0, d1 = acc[mt][nt][1] + bv1;
            float d2 = acc[mt][nt][2] + bv0, d3 = acc[mt][nt][3] + bv1;
            if (dorelu) {
                d0 = fmaxf(d0, 0.f); d1 = fmaxf(d1, 0.f);
                d2 = fmaxf(d2, 0.f); d3 = fmaxf(d3, 0.f);
            }
            size_t r0 = (size_t)m * ldc + n, r1 = (size_t)(m + 8) * ldc + n;
            uint32_t h01, l01, h23, l23;
            split2(d0, d1, h01, l01);
            split2(d2, d3, h23, l23);
            *(uint32_t*)&Shi[r0] = h01; *(uint32_t*)&Slo[r0] = l01;
            *(uint32_t*)&Shi[r1] = h23; *(uint32_t*)&Slo[r1] = l23;
        }
}

// ---------------- fused GATv2 attention + bias + residual + LayerNorm (2 pixels/block) ----------------
__global__ __launch_bounds__(256) void attn_ln(const float* __restrict__ att,
                                               const float* __restrict__ bias,
                                               const float* __restrict__ lng,
                                               const float* __restrict__ lnb,
                                               int writePC) {
    __shared__ float sxl[2][1024], sxr[2][1024], st[2][1024], satt[256];
    __shared__ float ssc[2][4][4][4], sal[2][4][4][4];
    int tid = threadIdx.x;
    int sub = tid >> 7, t = tid & 127;
    int p = blockIdx.x * 2 + sub;
    size_t base = (size_t)p * 1024;
#pragma unroll
    for (int q = 0; q < 2; q++) {
        int off = (t + q * 128) * 4;
        *(float4*)&sxl[sub][off] = *(const float4*)&g_XL[base + off];
        *(float4*)&sxr[sub][off] = *(const float4*)&g_XR[base + off];
        uint2 hv = *(const uint2*)&g_Xhi[base + off];
        uint2 lv = *(const uint2*)&g_Xlo[base + off];
        st[sub][off + 0] = bfu(hv.x & 0xffff) + bfu(lv.x & 0xffff);
        st[sub][off + 1] = bfu(hv.x >> 16)    + bfu(lv.x >> 16);
        st[sub][off + 2] = bfu(hv.y & 0xffff) + bfu(lv.y & 0xffff);
        st[sub][off + 3] = bfu(hv.y >> 16)    + bfu(lv.y >> 16);
    }
    if (tid < 64) *(float4*)&satt[tid * 4] = *(const float4*)&att[tid * 4];
    __syncthreads();
    int wi = t >> 5, lane = t & 31;
#pragma unroll
    for (int jh = 0; jh < 16; jh++) {
        int j = jh >> 2, hh = jh & 3;
        float partial = 0.f;
#pragma unroll
        for (int u = 0; u < 2; u++) {
            int c = hh * 64 + lane * 2 + u;
            float v = sxr[sub][wi * 256 + c] + sxl[sub][j * 256 + c];
            v = v > 0.f ? v : 0.2f * v;
            partial += satt[c] * v;
        }
#pragma unroll
        for (int off = 16; off; off >>= 1)
            partial += __shfl_xor_sync(0xffffffffu, partial, off);
        if (lane == 0) ssc[sub][wi][j][hh] = partial;
    }
    __syncthreads();
    if (t < 16) {
        int i = t >> 2, hh = t & 3;
        float s0 = ssc[sub][i][0][hh], s1 = ssc[sub][i][1][hh];
        float s2 = ssc[sub][i][2][hh], s3 = ssc[sub][i][3][hh];
        float mx = fmaxf(fmaxf(s0, s1), fmaxf(s2, s3));
        float e0 = expf(s0 - mx), e1 = expf(s1 - mx), e2 = expf(s2 - mx), e3 = expf(s3 - mx);
        float inv = 1.f / (e0 + e1 + e2 + e3);
        sal[sub][i][0][hh] = e0 * inv; sal[sub][i][1][hh] = e1 * inv;
        sal[sub][i][2][hh] = e2 * inv; sal[sub][i][3][hh] = e3 * inv;
    }
    __syncthreads();
    for (int q = t; q < 1024; q += 128) {
        int i = q >> 8, c = q & 255, hh = c >> 6;
        float o = sal[sub][i][0][hh] * sxl[sub][c] + sal[sub][i][1][hh] * sxl[sub][256 + c]
                + sal[sub][i][2][hh] * sxl[sub][512 + c] + sal[sub][i][3][hh] * sxl[sub][768 + c];
        st[sub][q] += o + bias[c];
    }
    __syncthreads();
    float sum = 0.f, sq = 0.f;
#pragma unroll
    for (int u = 0; u < 4; u++) {
        int c = 2 * lane + 64 * u;
        float v0 = st[sub][wi * 256 + c], v1 = st[sub][wi * 256 + c + 1];
        sum += v0 + v1; sq += v0 * v0 + v1 * v1;
    }
#pragma unroll
    for (int off = 16; off; off >>= 1) {
        sum += __shfl_xor_sync(0xffffffffu, sum, off);
        sq  += __shfl_xor_sync(0xffffffffu, sq, off);
    }
    float mu = sum * (1.f / 256.f);
    float var = sq * (1.f / 256.f) - mu * mu;
    float rstd = rsqrtf(var + 1e-5f);
#pragma unroll
    for (int u = 0; u < 4; u++) {
        int c = 2 * lane + 64 * u;
        float y0 = (st[sub][wi * 256 + c]     - mu) * rstd * lng[c]     + lnb[c];
        float y1 = (st[sub][wi * 256 + c + 1] - mu) * rstd * lng[c + 1] + lnb[c + 1];
        uint32_t h, l;
        split2(y0, y1, h, l);
        size_t a = base + wi * 256 + c;
        *(uint32_t*)&g_Xhi[a] = h;
        *(uint32_t*)&g_Xlo[a] = l;
        if (writePC && wi == 0) {
            *(uint32_t*)&g_PChi[(size_t)p * 256 + c] = h;
            *(uint32_t*)&g_PClo[(size_t)p * 256 + c] = l;
        }
    }
}

// ---------------- conv3x3+BN+ReLU+residual: halo A-tile shared across 3 dw shifts ----------------
__global__ __launch_bounds__(256, 2) void conv_mma(const float* __restrict__ bg,
                                                   const float* __restrict__ bb,
                                                   const float* __restrict__ bm,
                                                   const float* __restrict__ bv,
                                                   float* __restrict__ out) {
    extern __shared__ char smem[];
    uint32_t sb = cvta_s(smem);
    int tid = threadIdx.x, lane = tid & 31, wid = tid >> 5;
    int tile = blockIdx.x;
    int n0 = blockIdx.y * 64;
    int p0 = tile * 128;
    int b = tile >> 7, h = tile & 127;
    int mwarp = (wid & 3) * 32, nwarp = (wid >> 2) * 32;

    int dhs[3], nv = 0;
    for (int dh = -1; dh <= 1; dh++)
        if ((unsigned)(h + dh) < 128u) dhs[nv++] = dh;
    int S = nv * 8;

    float acc[2][4][4] = {};

    auto load_phase = [&](int s, int bf) {
        int dh = dhs[s >> 3], kc = s & 7;
        uint32_t stg = sb + bf * CBUF;
        int kk0 = kc * 32;
#pragma unroll
        for (int i = 0; i < 5; i++) {
            int idx = i * 256 + tid;
            if (idx < 1040) {
                int arr = idx >= 520;
                int cid = arr ? idx - 520 : idx;
                int row = cid >> 2, off = (cid & 3) * 16;
                int wpix = row - 1;
                int valid = (unsigned)wpix < 128u;
                int gp = p0 + dh * 128 + (valid ? wpix : 0);
                const __nv_bfloat16* src = (arr == 0)
                    ? &g_PChi[(size_t)gp * 256 + kk0 + (cid & 3) * 8]
                    : &g_PClo[(size_t)gp * 256 + kk0 + (cid & 3) * 8];
                cp16z(stg + arr * CA + SWO(row, off), src, valid);
            }
        }
        int qbase = (dh + 1) * 3;
#pragma unroll
        for (int i = 0; i < 6; i++) {
            int idx = i * 256 + tid;
            int qq = idx >> 9, r2 = idx & 511;
            int isLo = r2 >> 8, cid = r2 & 255;
            int row = cid >> 2, off = (cid & 3) * 16;
            const __nv_bfloat16* basep = isLo ? g_CWlo : g_CWhi;
            cp16(stg + BOFF + qq * 8192 + isLo * 4096 + SWO(row, off),
                 &basep[(size_t)(qbase + qq) * 65536 + (size_t)(n0 + row) * 256 + kk0 + (cid & 3) * 8]);
        }
        CP_COMMIT;
    };

    auto compute = [&](int bf) {
        uint32_t stg = sb + bf * CBUF;
        int colb = ((lane >> 4) << 4);
#pragma unroll
        for (int dwq = 0; dwq < 3; dwq++) {
            uint32_t b0 = stg + BOFF + dwq * 8192;
            uint32_t b1 = b0 + 4096;
#pragma unroll
            for (int ks = 0; ks < 2; ks++) {
                int cb = ks * 32 + colb;
                uint32_t ah[2][4], al[2][4];
#pragma unroll
                for (int mt = 0; mt < 2; mt++) {
                    int r = mwarp + mt * 16 + (lane & 15) + dwq;
                    ldsm4(ah[mt], stg + SWO(r, cb));
                    ldsm4(al[mt], stg + CA + SWO(r, cb));
                }
#pragma unroll
                for (int np = 0; np < 2; np++) {
                    int r = nwarp + np * 16 + (lane & 15);
                    uint32_t th[4], tl[4];
                    ldsm4(th, b0 + SWO(r, cb));
                    ldsm4(tl, b1 + SWO(r, cb));
                    uint32_t bh0[2] = {th[0], th[2]}, bh1[2] = {th[1], th[3]};
                    uint32_t bl0[2] = {tl[0], tl[2]}, bl1[2] = {tl[1], tl[3]};
                    mma16816(acc[0][2*np],   ah[0], bh0);
                    mma16816(acc[0][2*np+1], ah[0], bh1);
                    mma16816(acc[1][2*np],   ah[1], bh0);
                    mma16816(acc[1][2*np+1], ah[1], bh1);
                    mma16816(acc[0][2*np],   ah[0], bl0);
                    mma16816(acc[0][2*np+1], ah[0], bl1);
                    mma16816(acc[1][2*np],   ah[1], bl0);
                    mma16816(acc[1][2*np+1], ah[1], bl1);
                    mma16816(acc[0][2*np],   al[0], bh0);
                    mma16816(acc[0][2*np+1], al[0], bh1);
                    mma16816(acc[1][2*np],   al[1], bh0);
                    mma16816(acc[1][2*np+1], al[1], bh1);
                }
            }
        }
    };

    load_phase(0, 0);
    for (int s = 0; s < S; s++) {
        CP_WAIT0;
        __syncthreads();
        if (s + 1 < S) load_phase(s + 1, (s + 1) & 1);
        compute(s & 1);
    }

#pragma unroll
    for (int mt = 0; mt < 2; mt++)
#pragma unroll
        for (int nt = 0; nt < 4; nt++) {
            int w = mwarp + mt * 16 + (lane >> 2);
            int co = n0 + nwarp + nt * 8 + 2 * (lane & 3);
            float sc0 = bg[co] * rsqrtf(bv[co] + 1e-5f);
            float sh0 = bb[co] - bm[co] * sc0;
            float sc1 = bg[co+1] * rsqrtf(bv[co+1] + 1e-5f);
            float sh1 = bb[co+1] - bm[co+1] * sc1;
            float d[4] = {
                fmaf(acc[mt][nt][0], sc0, sh0), fmaf(acc[mt][nt][1], sc1, sh1),
                fmaf(acc[mt][nt][2], sc0, sh0), fmaf(acc[mt][nt][3], sc1, sh1) };
#pragma unroll
            for (int e = 0; e < 4; e++) d[e] = fmaxf(d[e], 0.f);
            int w2 = w + 8;
            uint32_t rh0 = *(const uint32_t*)&g_PChi[(size_t)(p0 + w) * 256 + co];
            uint32_t rl0 = *(const uint32_t*)&g_PClo[(size_t)(p0 + w) * 256 + co];
            uint32_t rh1 = *(const uint32_t*)&g_PChi[(size_t)(p0 + w2) * 256 + co];
            uint32_t rl1 = *(const uint32_t*)&g_PClo[(size_t)(p0 + w2) * 256 + co];
            d[0] += bfu(rh0 & 0xffff) + bfu(rl0 & 0xffff);
            d[1] += bfu(rh0 >> 16)    + bfu(rl0 >> 16);
            d[2] += bfu(rh1 & 0xffff) + bfu(rl1 & 0xffff);
            d[3] += bfu(rh1 >> 16)    + bfu(rl1 >> 16);
            out[(((size_t)(b * 256 + co)) * Hh + h) * Ww + w]       = d[0];
            out[(((size_t)(b * 256 + co + 1)) * Hh + h) * Ww + w]   = d[1];
            out[(((size_t)(b * 256 + co)) * Hh + h) * Ww + w2]      = d[2];
            out[(((size_t)(b * 256 + co + 1)) * Hh + h) * Ww + w2]  = d[3];
        }
}

// ---------------- launch ----------------
extern "C" void kernel_launch(void* const* d_in, const int* in_sizes, int n_in,
                              void* d_out, int out_size) {
    const float* m0 = (const float*)d_in[0];
    const float* m1 = (const float*)d_in[1];
    const float* m2 = (const float*)d_in[2];
    const float* fn_w1 = (const float*)d_in[3];
    const float* fn_b1 = (const float*)d_in[4];
    const float* fn_w2 = (const float*)d_in[5];
    const float* fn_b2 = (const float*)d_in[6];
    const float* l_wl[2]  = {(const float*)d_in[7],  (const float*)d_in[15]};
    const float* l_bl[2]  = {(const float*)d_in[8],  (const float*)d_in[16]};
    const float* l_wr[2]  = {(const float*)d_in[9],  (const float*)d_in[17]};
    const float* l_br[2]  = {(const float*)d_in[10], (const float*)d_in[18]};
    const float* l_att[2] = {(const float*)d_in[11], (const float*)d_in[19]};
    const float* l_bi[2]  = {(const float*)d_in[12], (const float*)d_in[20]};
    const float* ln_g[2]  = {(const float*)d_in[13], (const float*)d_in[21]};
    const float* ln_b[2]  = {(const float*)d_in[14], (const float*)d_in[22]};
    const float* conv_w = (const float*)d_in[23];
    const float* bn_g = (const float*)d_in[24];
    const float* bn_b = (const float*)d_in[25];
    const float* bn_m = (const float*)d_in[26];
    const float* bn_v = (const float*)d_in[27];
    float* out = (float*)d_out;

    static int inited = 0;
    if (!inited) {
        cudaFuncSetAttribute(gemm_cat,   cudaFuncAttributeMaxDynamicSharedMemorySize, GEMM_SMEM);
        cudaFuncSetAttribute(gemm_split, cudaFuncAttributeMaxDynamicSharedMemorySize, GEMM_SMEM);
        cudaFuncSetAttribute(conv_mma,   cudaFuncAttributeMaxDynamicSharedMemorySize, CONV_SMEM);
        inited = 1;
    }

    WPtrs wp;
    wp.p[0] = fn_w1; wp.p[1] = fn_w2;
    wp.p[2] = l_wl[0]; wp.p[3] = l_wr[0];
    wp.p[4] = l_wl[1]; wp.p[5] = l_wr[1];
    prep_all<<<dim3(256, 9, 3), 256>>>(wp, conv_w);

    build_nodes<<<dim3(Ptot / 32, 256 / 32), dim3(32, 8)>>>(m0, m1, m2);

    // fusion MLP: H1 = relu(mean@W1+b1); X node0 = H1@W2+b2
    gemm_split<<<dim3(Ptot / 64, 2), 128, GEMM_SMEM>>>(0, 0, fn_b1, 1, 256, 1);
    gemm_split<<<dim3(Ptot / 64, 2), 128, GEMM_SMEM>>>(2, 1, fn_b2, 2, 1024, 0);

    for (int l = 0; l < 2; l++) {
        gemm_cat<<<dim3(NODES / 64, 4), 128, GEMM_SMEM>>>(2 + 2 * l, l_bl[l], l_br[l]);
        attn_ln<<<Ptot / 2, 256>>>(l_att[l], l_bi[l], ln_g[l], ln_b[l], l == 1);
    }

    conv_mma<<<dim3(256, 4), 256, CONV_SMEM>>>(bn_g, bn_b, bn_m, bn_v, out);
}